// round 14
// baseline (speedup 1.0000x reference)
#include <cuda_runtime.h>
#include <cstdint>
#include <cstddef>

// Neural-CDE forward, R14 = R13 (best: 6.753ms) with ONE change:
// lipswish via tanh.approx.f32 — sigma(x) = 0.5*(1+tanh(x/2)) needs 1 MUFU
// instead of 2 (EX2+RCP), halving the MUFU-pipe queue (256->128 cyc/SMSP per
// lipswish phase) and shortening the epilogue critical chain (~44 -> ~24cyc).
// Calculated precision risk: tanh.approx abs err ~5e-4 -> predicted final
// rel_err ~1e-4-5e-4 vs 1e-3 threshold. Single-variable round for clean
// attribution; revert to __fdividef if rel_err fails.
// Config: 128 CTAs x 512 thr, MC=8, 8-way split-K, 4 cols/thread,
// fma.rn.f32x2 GEMM core, exact weight loads, cross-GEMM weight prefetch,
// group-local act-ready barriers, packed-f32x2 tree combine, packed proj.

#define T_N   128
#define IN_N  32
#define H_N   256
#define OUT_N 32
#define MC    8            // batch rows per CTA
#define BST   8            // activation buffer stride [dim][row]
#define NTH   512
#define NG    8            // split-K groups
#define NCT   64           // column-threads per group (4 cols each)
#define KSH   (H_N / NG)   // 32
#define KSI   (IN_N / NG)  // 4
#define RST   36           // reduction stride in floats (32 data + 4 pad)

#define BUF_FLOATS   (H_N * BST)            // 2048
#define RED_FLOATS   (NG * NCT * RST)       // 18432
#define SCR_FLOATS   768                    // proj partials: 3 quarters x 128 u64
#define SMEM_FLOATS  (2 * BUF_FLOATS + RED_FLOATS + SCR_FLOATS)
#define SMEM_BYTES   (SMEM_FLOATS * 4)      // 93184

typedef unsigned long long u64;

__device__ __forceinline__ u64 fma2(u64 a, u64 b, u64 c) {
    u64 d;
    asm("fma.rn.f32x2 %0, %1, %2, %3;" : "=l"(d) : "l"(a), "l"(b), "l"(c));
    return d;
}
__device__ __forceinline__ u64 add2(u64 a, u64 b) {
    u64 d;
    asm("add.rn.f32x2 %0, %1, %2;" : "=l"(d) : "l"(a), "l"(b));
    return d;
}
__device__ __forceinline__ u64 dup2(float x) {
    u64 d; unsigned int u = __float_as_uint(x);
    asm("mov.b64 %0, {%1, %2};" : "=l"(d) : "r"(u), "r"(u));
    return d;
}
__device__ __forceinline__ float2 unpk(u64 v) {
    unsigned int a, b;
    asm("mov.b64 {%0, %1}, %2;" : "=r"(a), "=r"(b) : "l"(v));
    return make_float2(__uint_as_float(a), __uint_as_float(b));
}
__device__ __forceinline__ float lipswish(float x) {
    // 0.909*x*sigmoid(x) = u + u*tanh(x/2), u = 0.4545*x  (1 MUFU, not 2)
    float t;
    asm("tanh.approx.f32 %0, %1;" : "=f"(t) : "f"(0.5f * x));
    float u = 0.4545f * x;
    return fmaf(u, t, u);
}
// 64-thread named barrier for split-K group kg (ids 1..8; 0 = __syncthreads).
__device__ __forceinline__ void gbar(int kg) {
    asm volatile("bar.sync %0, %1;" :: "r"(1 + kg), "r"(64) : "memory");
}

// Preload the first two 4-k-row weight blocks of a GEMM (guards compile out).
template <int KS>
__device__ __forceinline__ void wpre(const float* __restrict__ Wp,
                                     float4* __restrict__ wA,
                                     float4* __restrict__ wB)
{
#pragma unroll
    for (int j = 0; j < 4; j++) if (j < KS)     wA[j] = *(const float4*)(Wp + j * H_N);
#pragma unroll
    for (int j = 0; j < 4; j++) if (4 + j < KS) wB[j] = *(const float4*)(Wp + (4 + j) * H_N);
}

// Raw partial GEMM over KS k-rows, 4 columns, 8 rows. acc[c*4+p] packs rows
// (2p,2p+1) of local column c: p=0 -> ua.x, p=1 -> ua.y, p=2 -> ub.x,
// p=3 -> ub.y. Wp pre-offset to (koff, n0); bp pre-offset to koff. wA/wB hold
// the first two blocks (preloaded by caller before the previous barrier).
template <int KS>
__device__ __forceinline__ void gemmT4(const float* __restrict__ Wp,
                                       const float* __restrict__ bp,
                                       float4* __restrict__ wA,
                                       float4* __restrict__ wB,
                                       u64* __restrict__ acc)
{
#pragma unroll
    for (int i = 0; i < 16; i++) acc[i] = 0ull;

    ulonglong2 ua = *(const ulonglong2*)(bp);       // k-row 0: rows (0,1),(2,3)
    ulonglong2 ub = *(const ulonglong2*)(bp + 4);   //          rows (4,5),(6,7)

#pragma unroll
    for (int kb = 0; kb < KS; kb += 4) {
        float4 wN[4];
        const bool ldw = (kb + 8 < KS);
        if (ldw) {
#pragma unroll
            for (int j = 0; j < 4; j++) wN[j] = *(const float4*)(Wp + (kb + 8 + j) * H_N);
        }
#pragma unroll
        for (int j = 0; j < 4; j++) {
            if (kb + j >= KS) continue;                    // compile-time (KS=4 case)
            const int knext = kb + j + 1;
            ulonglong2 na, nb;
            const bool lda = (knext < KS);
            if (lda) {
                na = *(const ulonglong2*)(bp + knext * BST);
                nb = *(const ulonglong2*)(bp + knext * BST + 4);
            }
            u64 w0 = dup2(wA[j].x), w1 = dup2(wA[j].y);
            u64 w2 = dup2(wA[j].z), w3 = dup2(wA[j].w);
            acc[0]  = fma2(ua.x, w0, acc[0]);  acc[1]  = fma2(ua.y, w0, acc[1]);
            acc[2]  = fma2(ub.x, w0, acc[2]);  acc[3]  = fma2(ub.y, w0, acc[3]);
            acc[4]  = fma2(ua.x, w1, acc[4]);  acc[5]  = fma2(ua.y, w1, acc[5]);
            acc[6]  = fma2(ub.x, w1, acc[6]);  acc[7]  = fma2(ub.y, w1, acc[7]);
            acc[8]  = fma2(ua.x, w2, acc[8]);  acc[9]  = fma2(ua.y, w2, acc[9]);
            acc[10] = fma2(ub.x, w2, acc[10]); acc[11] = fma2(ub.y, w2, acc[11]);
            acc[12] = fma2(ua.x, w3, acc[12]); acc[13] = fma2(ua.y, w3, acc[13]);
            acc[14] = fma2(ub.x, w3, acc[14]); acc[15] = fma2(ub.y, w3, acc[15]);
            if (lda) { ua = na; ub = nb; }
        }
#pragma unroll
        for (int j = 0; j < 4; j++) wA[j] = wB[j];
        if (ldw) {
#pragma unroll
            for (int j = 0; j < 4; j++) wB[j] = wN[j];
        }
    }
}

// Deposit 32 raw floats (16 packed pairs) at redp: word layout c*8+m.
__device__ __forceinline__ void red_put(float* __restrict__ redp,
                                        const u64* __restrict__ acc)
{
#pragma unroll
    for (int c = 0; c < 4; c++) {
        *(ulonglong2*)(redp + c * 8)     = make_ulonglong2(acc[c * 4],     acc[c * 4 + 1]);
        *(ulonglong2*)(redp + c * 8 + 4) = make_ulonglong2(acc[c * 4 + 2], acc[c * 4 + 3]);
    }
}

// Sum the 8 group-partials for this thread's float4 via a packed-f32x2 tree.
__device__ __forceinline__ float4 combine8(const float* __restrict__ red,
                                           int ct_e, int off)
{
    const float* p = red + ct_e * RST + off;
    ulonglong2 v0 = *(const ulonglong2*)(p);
    ulonglong2 v1 = *(const ulonglong2*)(p + 1 * NCT * RST);
    ulonglong2 v2 = *(const ulonglong2*)(p + 2 * NCT * RST);
    ulonglong2 v3 = *(const ulonglong2*)(p + 3 * NCT * RST);
    ulonglong2 v4 = *(const ulonglong2*)(p + 4 * NCT * RST);
    ulonglong2 v5 = *(const ulonglong2*)(p + 5 * NCT * RST);
    ulonglong2 v6 = *(const ulonglong2*)(p + 6 * NCT * RST);
    ulonglong2 v7 = *(const ulonglong2*)(p + 7 * NCT * RST);
    u64 ax = add2(add2(add2(v0.x, v1.x), add2(v2.x, v3.x)),
                  add2(add2(v4.x, v5.x), add2(v6.x, v7.x)));
    u64 ay = add2(add2(add2(v0.y, v1.y), add2(v2.y, v3.y)),
                  add2(add2(v4.y, v5.y), add2(v6.y, v7.y)));
    float2 lo = unpk(ax), hi = unpk(ay);
    return make_float4(lo.x, lo.y, hi.x, hi.y);
}

// Packed projection partial over one K-quarter: 2 output columns per thread.
__device__ __forceinline__ u64 proj_part2(const float* __restrict__ buf,
                                          const float* __restrict__ Wd,
                                          u64 bd2, int q, int r, int cp)
{
    u64 s2 = (q == 0) ? bd2 : 0ull;
    const int k0 = q * (H_N / 4);
    const float* wp = Wd + 2 * cp;
#pragma unroll 8
    for (int kk = k0; kk < k0 + H_N / 4; kk++) {
        u64 w = *(const u64*)(wp + kk * OUT_N);
        s2 = fma2(dup2(buf[kk * BST + r]), w, s2);
    }
    return s2;
}

__global__ void __launch_bounds__(NTH, 1)
cde_kernel(const float* __restrict__ coeffs, const float* __restrict__ times,
           const float* __restrict__ Wi,     const float* __restrict__ bi,
           const float* __restrict__ Wf,     const float* __restrict__ bfb,
           const float* __restrict__ Wd,     const float* __restrict__ bd,
           float* __restrict__ out)
{
    extern __shared__ float smem[];
    float* bufA = smem;                                  // 2048 floats
    float* bufB = smem + BUF_FLOATS;                     // 2048 floats
    float* red  = smem + 2 * BUF_FLOATS;                 // 18432 floats
    u64*   scr  = (u64*)(smem + 2 * BUF_FLOATS + RED_FLOATS);  // 3*128 u64

    const int tid   = threadIdx.x;
    const int kg    = tid >> 6;                 // split-K group 0..7
    const int ct    = tid & 63;                 // column-thread in group
    const int n0    = ct * 4;
    const int bbase = blockIdx.x * MC;

    // combine/update mapping: thread owns column n_e, rows m0..m0+3.
    const int ct_e = tid >> 3;
    const int sub  = tid & 7;
    const int c_e  = sub >> 1;
    const int m0   = (sub & 1) * 4;
    const int n_e  = ct_e * 4 + c_e;
    const int off  = c_e * 8 + m0;

    // projection mapping: 128 units (8 rows x 16 col-pairs) x 4 K-quarters
    const int p_q    = tid >> 7;                // K-quarter 0..3
    const int p_unit = tid & 127;
    const int p_r    = p_unit >> 4;             // batch row 0..7
    const int p_cp   = p_unit & 15;             // col-pair 0..15

    float* redp = red + (kg * NCT + ct) * RST;
    u64 acc[16];
    float4 wA[4], wB[4];

    // loop-invariant scalars hoisted off the combine critical path
    const float bias0 = bfb[0 * H_N + n_e];
    const float bias1 = bfb[1 * H_N + n_e];
    const float bias2 = bfb[2 * H_N + n_e];
    const float bias3 = bfb[3 * H_N + n_e];
    const u64   bd2   = *(const u64*)(bd + 2 * p_cp);

    // per-thread weight base for the hidden layers
    const size_t HH = (size_t)H_N * H_N;
    const float* W0 = Wf + (size_t)kg * KSH * H_N + n0;
    const int kact  = kg * KSH * BST;           // act offset for hidden GEMMs

    // hoisted output base for this thread's projection writes
    float* outp = out + (size_t)(bbase + p_r) * T_N * OUT_N + 2 * p_cp;

    // ---- stage coeffs[:,0,:] -> bufA[k][m] ----
    if (tid < 256) {
        int m = tid >> 5, kk = tid & 31;
        bufA[kk * BST + m] = coeffs[(size_t)(bbase + m) * T_N * IN_N + kk];
    }

    // preload init-GEMM weights (KSI=4: one block) while staging lands
    wpre<KSI>(Wi + (size_t)kg * KSI * H_N + n0, wA, wB);
    __syncthreads();

    // ---- y0 = coeffs0 @ Wi + bi ----
    float y[4], ksum[4];
    gemmT4<KSI>(Wi + (size_t)kg * KSI * H_N + n0, bufA + kg * KSI * BST, wA, wB, acc);
    red_put(redp, acc);
    wpre<KSH>(W0, wA, wB);                      // prefetch layer-0 weights
    __syncthreads();
    {
        float4 v = combine8(red, ct_e, off);
        float bb = bi[n_e];
        y[0] = v.x + bb; y[1] = v.y + bb; y[2] = v.z + bb; y[3] = v.w + bb;
        *(float4*)(bufA + n_e * BST + m0) = make_float4(y[0], y[1], y[2], y[3]);
    }
    __syncthreads();            // full: next proj (st0/l0) reads ALL columns

    // ---- time loop; proj of y_t folded into stage-0/layer-0 of step t ----
#pragma unroll 1
    for (int t = 0; t < T_N - 1; t++) {
        const float dt = times[t + 1] - times[t];

#pragma unroll 1
        for (int st = 0; st < 4; st++) {
            float* in = bufA; float* ob = bufB;
            u64 ps2 = 0ull;
#pragma unroll 1
            for (int l = 0; l < 3; l++) {
                if (st == 0 && l == 0) {
                    // projection partial of y_t (bufA stable through this GEMM)
                    ps2 = proj_part2(bufA, Wd, bd2, p_q, p_r, p_cp);
                    if (p_q) scr[(p_q - 1) * 128 + p_unit] = ps2;
                }
                gemmT4<KSH>(W0 + l * HH, in + kact, wA, wB, acc);
                red_put(redp, acc);
                wpre<KSH>(W0 + (l + 1) * HH, wA, wB);   // prefetch next layer
                __syncthreads();     // full: deposits cross all groups (+scr)
                if (st == 0 && l == 0 && p_q == 0) {
                    u64 s = add2(add2(ps2, scr[p_unit]),
                                 add2(scr[128 + p_unit], scr[256 + p_unit]));
                    *(float2*)(outp + (size_t)t * OUT_N) = unpk(s);
                }
                float4 v = combine8(red, ct_e, off);
                float bb = (l == 0) ? bias0 : (l == 1) ? bias1 : bias2;
                v.x = lipswish(v.x + bb); v.y = lipswish(v.y + bb);
                v.z = lipswish(v.z + bb); v.w = lipswish(v.w + bb);
                *(float4*)(ob + n_e * BST + m0) = v;
                gbar(kg);            // group-local: own GEMM reads own columns
                float* tmp = in; in = ob; ob = tmp;
            }
            gemmT4<KSH>(W0 + 3 * HH, in + kact, wA, wB, acc);
            red_put(redp, acc);
            wpre<KSH>(W0, wA, wB);                      // prefetch next stage L0
            __syncthreads();         // full: deposits cross all groups
            float4 kv = combine8(red, ct_e, off);
            kv.x += bias3; kv.y += bias3; kv.z += bias3; kv.w += bias3;
            float k4[4] = {kv.x, kv.y, kv.z, kv.w};
            float s4[4];
            if (st == 0) {
#pragma unroll
                for (int i = 0; i < 4; i++) { ksum[i] = k4[i]; s4[i] = fmaf(0.5f * dt, k4[i], y[i]); }
            } else if (st == 1) {
#pragma unroll
                for (int i = 0; i < 4; i++) { ksum[i] = fmaf(2.f, k4[i], ksum[i]); s4[i] = fmaf(0.5f * dt, k4[i], y[i]); }
            } else if (st == 2) {
#pragma unroll
                for (int i = 0; i < 4; i++) { ksum[i] = fmaf(2.f, k4[i], ksum[i]); s4[i] = fmaf(dt, k4[i], y[i]); }
            } else {
#pragma unroll
                for (int i = 0; i < 4; i++) { ksum[i] += k4[i]; y[i] = fmaf(dt * (1.f / 6.f), ksum[i], y[i]); s4[i] = y[i]; }
            }
            *(float4*)(bufA + n_e * BST + m0) = make_float4(s4[0], s4[1], s4[2], s4[3]);
            if (st < 3) gbar(kg);    // group-local: next stage L0 reads own cols
            else        __syncthreads();   // full: st0/l0 proj reads ALL columns
        }
    }

    // ---- final projection of y_{T-1} ----
    {
        u64 ps2 = proj_part2(bufA, Wd, bd2, p_q, p_r, p_cp);
        if (p_q) scr[(p_q - 1) * 128 + p_unit] = ps2;
        __syncthreads();
        if (p_q == 0) {
            u64 s = add2(add2(ps2, scr[p_unit]),
                         add2(scr[128 + p_unit], scr[256 + p_unit]));
            *(float2*)(outp + (size_t)(T_N - 1) * OUT_N) = unpk(s);
        }
    }
}

extern "C" void kernel_launch(void* const* d_in, const int* in_sizes, int n_in,
                              void* d_out, int out_size)
{
    const float* coeffs = (const float*)d_in[0];
    const float* times  = (const float*)d_in[1];
    const float* Wi     = (const float*)d_in[2];
    const float* bi     = (const float*)d_in[3];
    const float* Wf     = (const float*)d_in[4];
    const float* bf     = (const float*)d_in[5];
    const float* Wd     = (const float*)d_in[6];
    const float* bd     = (const float*)d_in[7];
    float* out = (float*)d_out;

    cudaFuncSetAttribute(cde_kernel,
                         cudaFuncAttributeMaxDynamicSharedMemorySize, SMEM_BYTES);

    const int B    = in_sizes[0] / (T_N * IN_N);   // 1024
    const int grid = B / MC;                       // 128
    cde_kernel<<<grid, NTH, SMEM_BYTES>>>(coeffs, times, Wi, bi, Wf, bf, Wd, bd, out);
}

// round 15
// speedup vs baseline: 1.0448x; 1.0448x over previous
#include <cuda_runtime.h>
#include <cstdint>
#include <cstddef>

// Neural-CDE forward, R15 = R13 (best: 6.753ms; R14's tanh.approx regressed
// +4.4% and is reverted) plus two zero-math-change micro-fixes:
//  (a) QUARTER barriers at stage-3 end and post-y0: proj-quarter q reads
//      exactly bufA cols [64q,64q+64) = written by threads [128q,128q+128),
//      and each group's GEMM cols are a subset of its own quarter -> the
//      full __syncthreads becomes bar.sync(9+q, 128) (4-warp convergence).
//  (b) proj k-loop unroll 8 -> 16.
// Config: 128 CTAs x 512 thr, MC=8, 8-way split-K, 4 cols/thread,
// fma.rn.f32x2 GEMM core, exact weight loads, cross-GEMM weight prefetch,
// group-local act-ready barriers, packed-f32x2 tree combine, packed proj,
// __fdividef lipswish (validated: rel_err 2.85e-7).

#define T_N   128
#define IN_N  32
#define H_N   256
#define OUT_N 32
#define MC    8            // batch rows per CTA
#define BST   8            // activation buffer stride [dim][row]
#define NTH   512
#define NG    8            // split-K groups
#define NCT   64           // column-threads per group (4 cols each)
#define KSH   (H_N / NG)   // 32
#define KSI   (IN_N / NG)  // 4
#define RST   36           // reduction stride in floats (32 data + 4 pad)

#define BUF_FLOATS   (H_N * BST)            // 2048
#define RED_FLOATS   (NG * NCT * RST)       // 18432
#define SCR_FLOATS   768                    // proj partials: 3 quarters x 128 u64
#define SMEM_FLOATS  (2 * BUF_FLOATS + RED_FLOATS + SCR_FLOATS)
#define SMEM_BYTES   (SMEM_FLOATS * 4)      // 93184

typedef unsigned long long u64;

__device__ __forceinline__ u64 fma2(u64 a, u64 b, u64 c) {
    u64 d;
    asm("fma.rn.f32x2 %0, %1, %2, %3;" : "=l"(d) : "l"(a), "l"(b), "l"(c));
    return d;
}
__device__ __forceinline__ u64 add2(u64 a, u64 b) {
    u64 d;
    asm("add.rn.f32x2 %0, %1, %2;" : "=l"(d) : "l"(a), "l"(b));
    return d;
}
__device__ __forceinline__ u64 dup2(float x) {
    u64 d; unsigned int u = __float_as_uint(x);
    asm("mov.b64 %0, {%1, %2};" : "=l"(d) : "r"(u), "r"(u));
    return d;
}
__device__ __forceinline__ float2 unpk(u64 v) {
    unsigned int a, b;
    asm("mov.b64 {%0, %1}, %2;" : "=r"(a), "=r"(b) : "l"(v));
    return make_float2(__uint_as_float(a), __uint_as_float(b));
}
__device__ __forceinline__ float lipswish(float x) {
    // 0.909*x*sigmoid(x); __fdividef -> MUFU.RCP (validated in R12/R13)
    return __fdividef(0.909f * x, 1.0f + __expf(-x));
}
// 64-thread named barrier for split-K group kg (ids 1..8).
__device__ __forceinline__ void gbar(int kg) {
    asm volatile("bar.sync %0, %1;" :: "r"(1 + kg), "r"(64) : "memory");
}
// 128-thread named barrier for proj/act quarter q (ids 9..12).
__device__ __forceinline__ void qbar(int q) {
    asm volatile("bar.sync %0, %1;" :: "r"(9 + q), "r"(128) : "memory");
}

// Preload the first two 4-k-row weight blocks of a GEMM (guards compile out).
template <int KS>
__device__ __forceinline__ void wpre(const float* __restrict__ Wp,
                                     float4* __restrict__ wA,
                                     float4* __restrict__ wB)
{
#pragma unroll
    for (int j = 0; j < 4; j++) if (j < KS)     wA[j] = *(const float4*)(Wp + j * H_N);
#pragma unroll
    for (int j = 0; j < 4; j++) if (4 + j < KS) wB[j] = *(const float4*)(Wp + (4 + j) * H_N);
}

// Raw partial GEMM over KS k-rows, 4 columns, 8 rows. acc[c*4+p] packs rows
// (2p,2p+1) of local column c: p=0 -> ua.x, p=1 -> ua.y, p=2 -> ub.x,
// p=3 -> ub.y. Wp pre-offset to (koff, n0); bp pre-offset to koff. wA/wB hold
// the first two blocks (preloaded by caller before the previous barrier).
template <int KS>
__device__ __forceinline__ void gemmT4(const float* __restrict__ Wp,
                                       const float* __restrict__ bp,
                                       float4* __restrict__ wA,
                                       float4* __restrict__ wB,
                                       u64* __restrict__ acc)
{
#pragma unroll
    for (int i = 0; i < 16; i++) acc[i] = 0ull;

    ulonglong2 ua = *(const ulonglong2*)(bp);       // k-row 0: rows (0,1),(2,3)
    ulonglong2 ub = *(const ulonglong2*)(bp + 4);   //          rows (4,5),(6,7)

#pragma unroll
    for (int kb = 0; kb < KS; kb += 4) {
        float4 wN[4];
        const bool ldw = (kb + 8 < KS);
        if (ldw) {
#pragma unroll
            for (int j = 0; j < 4; j++) wN[j] = *(const float4*)(Wp + (kb + 8 + j) * H_N);
        }
#pragma unroll
        for (int j = 0; j < 4; j++) {
            if (kb + j >= KS) continue;                    // compile-time (KS=4 case)
            const int knext = kb + j + 1;
            ulonglong2 na, nb;
            const bool lda = (knext < KS);
            if (lda) {
                na = *(const ulonglong2*)(bp + knext * BST);
                nb = *(const ulonglong2*)(bp + knext * BST + 4);
            }
            u64 w0 = dup2(wA[j].x), w1 = dup2(wA[j].y);
            u64 w2 = dup2(wA[j].z), w3 = dup2(wA[j].w);
            acc[0]  = fma2(ua.x, w0, acc[0]);  acc[1]  = fma2(ua.y, w0, acc[1]);
            acc[2]  = fma2(ub.x, w0, acc[2]);  acc[3]  = fma2(ub.y, w0, acc[3]);
            acc[4]  = fma2(ua.x, w1, acc[4]);  acc[5]  = fma2(ua.y, w1, acc[5]);
            acc[6]  = fma2(ub.x, w1, acc[6]);  acc[7]  = fma2(ub.y, w1, acc[7]);
            acc[8]  = fma2(ua.x, w2, acc[8]);  acc[9]  = fma2(ua.y, w2, acc[9]);
            acc[10] = fma2(ub.x, w2, acc[10]); acc[11] = fma2(ub.y, w2, acc[11]);
            acc[12] = fma2(ua.x, w3, acc[12]); acc[13] = fma2(ua.y, w3, acc[13]);
            acc[14] = fma2(ub.x, w3, acc[14]); acc[15] = fma2(ub.y, w3, acc[15]);
            if (lda) { ua = na; ub = nb; }
        }
#pragma unroll
        for (int j = 0; j < 4; j++) wA[j] = wB[j];
        if (ldw) {
#pragma unroll
            for (int j = 0; j < 4; j++) wB[j] = wN[j];
        }
    }
}

// Deposit 32 raw floats (16 packed pairs) at redp: word layout c*8+m.
__device__ __forceinline__ void red_put(float* __restrict__ redp,
                                        const u64* __restrict__ acc)
{
#pragma unroll
    for (int c = 0; c < 4; c++) {
        *(ulonglong2*)(redp + c * 8)     = make_ulonglong2(acc[c * 4],     acc[c * 4 + 1]);
        *(ulonglong2*)(redp + c * 8 + 4) = make_ulonglong2(acc[c * 4 + 2], acc[c * 4 + 3]);
    }
}

// Sum the 8 group-partials for this thread's float4 via a packed-f32x2 tree.
__device__ __forceinline__ float4 combine8(const float* __restrict__ red,
                                           int ct_e, int off)
{
    const float* p = red + ct_e * RST + off;
    ulonglong2 v0 = *(const ulonglong2*)(p);
    ulonglong2 v1 = *(const ulonglong2*)(p + 1 * NCT * RST);
    ulonglong2 v2 = *(const ulonglong2*)(p + 2 * NCT * RST);
    ulonglong2 v3 = *(const ulonglong2*)(p + 3 * NCT * RST);
    ulonglong2 v4 = *(const ulonglong2*)(p + 4 * NCT * RST);
    ulonglong2 v5 = *(const ulonglong2*)(p + 5 * NCT * RST);
    ulonglong2 v6 = *(const ulonglong2*)(p + 6 * NCT * RST);
    ulonglong2 v7 = *(const ulonglong2*)(p + 7 * NCT * RST);
    u64 ax = add2(add2(add2(v0.x, v1.x), add2(v2.x, v3.x)),
                  add2(add2(v4.x, v5.x), add2(v6.x, v7.x)));
    u64 ay = add2(add2(add2(v0.y, v1.y), add2(v2.y, v3.y)),
                  add2(add2(v4.y, v5.y), add2(v6.y, v7.y)));
    float2 lo = unpk(ax), hi = unpk(ay);
    return make_float4(lo.x, lo.y, hi.x, hi.y);
}

// Packed projection partial over one K-quarter: 2 output columns per thread.
__device__ __forceinline__ u64 proj_part2(const float* __restrict__ buf,
                                          const float* __restrict__ Wd,
                                          u64 bd2, int q, int r, int cp)
{
    u64 s2 = (q == 0) ? bd2 : 0ull;
    const int k0 = q * (H_N / 4);
    const float* wp = Wd + 2 * cp;
#pragma unroll 16
    for (int kk = k0; kk < k0 + H_N / 4; kk++) {
        u64 w = *(const u64*)(wp + kk * OUT_N);
        s2 = fma2(dup2(buf[kk * BST + r]), w, s2);
    }
    return s2;
}

__global__ void __launch_bounds__(NTH, 1)
cde_kernel(const float* __restrict__ coeffs, const float* __restrict__ times,
           const float* __restrict__ Wi,     const float* __restrict__ bi,
           const float* __restrict__ Wf,     const float* __restrict__ bfb,
           const float* __restrict__ Wd,     const float* __restrict__ bd,
           float* __restrict__ out)
{
    extern __shared__ float smem[];
    float* bufA = smem;                                  // 2048 floats
    float* bufB = smem + BUF_FLOATS;                     // 2048 floats
    float* red  = smem + 2 * BUF_FLOATS;                 // 18432 floats
    u64*   scr  = (u64*)(smem + 2 * BUF_FLOATS + RED_FLOATS);  // 3*128 u64

    const int tid   = threadIdx.x;
    const int kg    = tid >> 6;                 // split-K group 0..7
    const int ct    = tid & 63;                 // column-thread in group
    const int n0    = ct * 4;
    const int bbase = blockIdx.x * MC;

    // combine/update mapping: thread owns column n_e, rows m0..m0+3.
    // Quarter q = tid>>7 writes act columns [64q, 64q+64) — exactly the
    // columns proj-quarter q reads, and a superset of each member group's
    // GEMM k-slice -> st3/y0 act sync is quarter-local (qbar).
    const int ct_e = tid >> 3;
    const int sub  = tid & 7;
    const int c_e  = sub >> 1;
    const int m0   = (sub & 1) * 4;
    const int n_e  = ct_e * 4 + c_e;
    const int off  = c_e * 8 + m0;

    // projection mapping: 128 units (8 rows x 16 col-pairs) x 4 K-quarters
    const int p_q    = tid >> 7;                // K-quarter 0..3
    const int p_unit = tid & 127;
    const int p_r    = p_unit >> 4;             // batch row 0..7
    const int p_cp   = p_unit & 15;             // col-pair 0..15

    float* redp = red + (kg * NCT + ct) * RST;
    u64 acc[16];
    float4 wA[4], wB[4];

    // loop-invariant scalars hoisted off the combine critical path
    const float bias0 = bfb[0 * H_N + n_e];
    const float bias1 = bfb[1 * H_N + n_e];
    const float bias2 = bfb[2 * H_N + n_e];
    const float bias3 = bfb[3 * H_N + n_e];
    const u64   bd2   = *(const u64*)(bd + 2 * p_cp);

    // per-thread weight base for the hidden layers
    const size_t HH = (size_t)H_N * H_N;
    const float* W0 = Wf + (size_t)kg * KSH * H_N + n0;
    const int kact  = kg * KSH * BST;           // act offset for hidden GEMMs

    // hoisted output base for this thread's projection writes
    float* outp = out + (size_t)(bbase + p_r) * T_N * OUT_N + 2 * p_cp;

    // ---- stage coeffs[:,0,:] -> bufA[k][m] ----
    if (tid < 256) {
        int m = tid >> 5, kk = tid & 31;
        bufA[kk * BST + m] = coeffs[(size_t)(bbase + m) * T_N * IN_N + kk];
    }

    // preload init-GEMM weights (KSI=4: one block) while staging lands
    wpre<KSI>(Wi + (size_t)kg * KSI * H_N + n0, wA, wB);
    __syncthreads();

    // ---- y0 = coeffs0 @ Wi + bi ----
    float y[4], ksum[4];
    gemmT4<KSI>(Wi + (size_t)kg * KSI * H_N + n0, bufA + kg * KSI * BST, wA, wB, acc);
    red_put(redp, acc);
    wpre<KSH>(W0, wA, wB);                      // prefetch layer-0 weights
    __syncthreads();
    {
        float4 v = combine8(red, ct_e, off);
        float bb = bi[n_e];
        y[0] = v.x + bb; y[1] = v.y + bb; y[2] = v.z + bb; y[3] = v.w + bb;
        *(float4*)(bufA + n_e * BST + m0) = make_float4(y[0], y[1], y[2], y[3]);
    }
    qbar(p_q);                  // quarter-local: proj+GEMM read own quarter

    // ---- time loop; proj of y_t folded into stage-0/layer-0 of step t ----
#pragma unroll 1
    for (int t = 0; t < T_N - 1; t++) {
        const float dt = times[t + 1] - times[t];

#pragma unroll 1
        for (int st = 0; st < 4; st++) {
            float* in = bufA; float* ob = bufB;
            u64 ps2 = 0ull;
#pragma unroll 1
            for (int l = 0; l < 3; l++) {
                if (st == 0 && l == 0) {
                    // projection partial of y_t (bufA stable through this GEMM)
                    ps2 = proj_part2(bufA, Wd, bd2, p_q, p_r, p_cp);
                    if (p_q) scr[(p_q - 1) * 128 + p_unit] = ps2;
                }
                gemmT4<KSH>(W0 + l * HH, in + kact, wA, wB, acc);
                red_put(redp, acc);
                wpre<KSH>(W0 + (l + 1) * HH, wA, wB);   // prefetch next layer
                __syncthreads();     // full: deposits cross all groups (+scr)
                if (st == 0 && l == 0 && p_q == 0) {
                    u64 s = add2(add2(ps2, scr[p_unit]),
                                 add2(scr[128 + p_unit], scr[256 + p_unit]));
                    *(float2*)(outp + (size_t)t * OUT_N) = unpk(s);
                }
                float4 v = combine8(red, ct_e, off);
                float bb = (l == 0) ? bias0 : (l == 1) ? bias1 : bias2;
                v.x = lipswish(v.x + bb); v.y = lipswish(v.y + bb);
                v.z = lipswish(v.z + bb); v.w = lipswish(v.w + bb);
                *(float4*)(ob + n_e * BST + m0) = v;
                gbar(kg);            // group-local: own GEMM reads own columns
                float* tmp = in; in = ob; ob = tmp;
            }
            gemmT4<KSH>(W0 + 3 * HH, in + kact, wA, wB, acc);
            red_put(redp, acc);
            wpre<KSH>(W0, wA, wB);                      // prefetch next stage L0
            __syncthreads();         // full: deposits cross all groups
            float4 kv = combine8(red, ct_e, off);
            kv.x += bias3; kv.y += bias3; kv.z += bias3; kv.w += bias3;
            float k4[4] = {kv.x, kv.y, kv.z, kv.w};
            float s4[4];
            if (st == 0) {
#pragma unroll
                for (int i = 0; i < 4; i++) { ksum[i] = k4[i]; s4[i] = fmaf(0.5f * dt, k4[i], y[i]); }
            } else if (st == 1) {
#pragma unroll
                for (int i = 0; i < 4; i++) { ksum[i] = fmaf(2.f, k4[i], ksum[i]); s4[i] = fmaf(0.5f * dt, k4[i], y[i]); }
            } else if (st == 2) {
#pragma unroll
                for (int i = 0; i < 4; i++) { ksum[i] = fmaf(2.f, k4[i], ksum[i]); s4[i] = fmaf(dt, k4[i], y[i]); }
            } else {
#pragma unroll
                for (int i = 0; i < 4; i++) { ksum[i] += k4[i]; y[i] = fmaf(dt * (1.f / 6.f), ksum[i], y[i]); s4[i] = y[i]; }
            }
            *(float4*)(bufA + n_e * BST + m0) = make_float4(s4[0], s4[1], s4[2], s4[3]);
            if (st < 3) gbar(kg);    // group-local: next stage L0 reads own cols
            else        qbar(p_q);   // quarter-local: st0/l0 proj+GEMM per quarter
        }
    }

    // ---- final projection of y_{T-1} ----
    {
        u64 ps2 = proj_part2(bufA, Wd, bd2, p_q, p_r, p_cp);
        if (p_q) scr[(p_q - 1) * 128 + p_unit] = ps2;
        __syncthreads();
        if (p_q == 0) {
            u64 s = add2(add2(ps2, scr[p_unit]),
                         add2(scr[128 + p_unit], scr[256 + p_unit]));
            *(float2*)(outp + (size_t)(T_N - 1) * OUT_N) = unpk(s);
        }
    }
}

extern "C" void kernel_launch(void* const* d_in, const int* in_sizes, int n_in,
                              void* d_out, int out_size)
{
    const float* coeffs = (const float*)d_in[0];
    const float* times  = (const float*)d_in[1];
    const float* Wi     = (const float*)d_in[2];
    const float* bi     = (const float*)d_in[3];
    const float* Wf     = (const float*)d_in[4];
    const float* bf     = (const float*)d_in[5];
    const float* Wd     = (const float*)d_in[6];
    const float* bd     = (const float*)d_in[7];
    float* out = (float*)d_out;

    cudaFuncSetAttribute(cde_kernel,
                         cudaFuncAttributeMaxDynamicSharedMemorySize, SMEM_BYTES);

    const int B    = in_sizes[0] / (T_N * IN_N);   // 1024
    const int grid = B / MC;                       // 128
    cde_kernel<<<grid, NTH, SMEM_BYTES>>>(coeffs, times, Wi, bi, Wf, bf, Wd, bd, out);
}

// round 16
// speedup vs baseline: 1.0732x; 1.0272x over previous
#include <cuda_runtime.h>
#include <cstdint>
#include <cstddef>

// Neural-CDE forward, R16 = R15 (best: 6.750ms) + epilogue-chain micro-bundle
// (all bit-exact packings, no math reorder):
//  (a) packed RK4 stage-boundary: y/ksum held as f32x2 pairs, bias/update via
//      add2/fma2 — fewer issues + shorter deps on the stage-boundary chain;
//  (b) packed bias-add in lipswish phases (add2 before unpack);
//  (c) times[] staged to SMEM once (dt = LDS, not loop-top LDG).
// Config: 128 CTAs x 512 thr, MC=8, 8-way split-K, 4 cols/thread,
// fma.rn.f32x2 GEMM core, exact weight loads, cross-GEMM weight prefetch,
// group-local (gbar) + quarter (qbar) barriers, packed tree combine,
// packed proj, __fdividef lipswish.

#define T_N   128
#define IN_N  32
#define H_N   256
#define OUT_N 32
#define MC    8            // batch rows per CTA
#define BST   8            // activation buffer stride [dim][row]
#define NTH   512
#define NG    8            // split-K groups
#define NCT   64           // column-threads per group (4 cols each)
#define KSH   (H_N / NG)   // 32
#define KSI   (IN_N / NG)  // 4
#define RST   36           // reduction stride in floats (32 data + 4 pad)

#define BUF_FLOATS   (H_N * BST)            // 2048
#define RED_FLOATS   (NG * NCT * RST)       // 18432
#define SCR_FLOATS   768                    // proj partials: 3 quarters x 128 u64
#define TIM_FLOATS   T_N                    // staged times
#define SMEM_FLOATS  (2 * BUF_FLOATS + RED_FLOATS + SCR_FLOATS + TIM_FLOATS)
#define SMEM_BYTES   (SMEM_FLOATS * 4)      // 93696

typedef unsigned long long u64;

__device__ __forceinline__ u64 fma2(u64 a, u64 b, u64 c) {
    u64 d;
    asm("fma.rn.f32x2 %0, %1, %2, %3;" : "=l"(d) : "l"(a), "l"(b), "l"(c));
    return d;
}
__device__ __forceinline__ u64 add2(u64 a, u64 b) {
    u64 d;
    asm("add.rn.f32x2 %0, %1, %2;" : "=l"(d) : "l"(a), "l"(b));
    return d;
}
__device__ __forceinline__ u64 dup2(float x) {
    u64 d; unsigned int u = __float_as_uint(x);
    asm("mov.b64 %0, {%1, %2};" : "=l"(d) : "r"(u), "r"(u));
    return d;
}
__device__ __forceinline__ float2 unpk(u64 v) {
    unsigned int a, b;
    asm("mov.b64 {%0, %1}, %2;" : "=r"(a), "=r"(b) : "l"(v));
    return make_float2(__uint_as_float(a), __uint_as_float(b));
}
__device__ __forceinline__ u64 pk2(float x, float y) {
    u64 d; unsigned int a = __float_as_uint(x), b = __float_as_uint(y);
    asm("mov.b64 %0, {%1, %2};" : "=l"(d) : "r"(a), "r"(b));
    return d;
}
__device__ __forceinline__ float lipswish(float x) {
    // 0.909*x*sigmoid(x); __fdividef -> MUFU.RCP (validated R12/R13)
    return __fdividef(0.909f * x, 1.0f + __expf(-x));
}
// 64-thread named barrier for split-K group kg (ids 1..8).
__device__ __forceinline__ void gbar(int kg) {
    asm volatile("bar.sync %0, %1;" :: "r"(1 + kg), "r"(64) : "memory");
}
// 128-thread named barrier for proj/act quarter q (ids 9..12).
__device__ __forceinline__ void qbar(int q) {
    asm volatile("bar.sync %0, %1;" :: "r"(9 + q), "r"(128) : "memory");
}

// Preload the first two 4-k-row weight blocks of a GEMM (guards compile out).
template <int KS>
__device__ __forceinline__ void wpre(const float* __restrict__ Wp,
                                     float4* __restrict__ wA,
                                     float4* __restrict__ wB)
{
#pragma unroll
    for (int j = 0; j < 4; j++) if (j < KS)     wA[j] = *(const float4*)(Wp + j * H_N);
#pragma unroll
    for (int j = 0; j < 4; j++) if (4 + j < KS) wB[j] = *(const float4*)(Wp + (4 + j) * H_N);
}

// Raw partial GEMM over KS k-rows, 4 columns, 8 rows. acc[c*4+p] packs rows
// (2p,2p+1) of local column c: p=0 -> ua.x, p=1 -> ua.y, p=2 -> ub.x,
// p=3 -> ub.y. Wp pre-offset to (koff, n0); bp pre-offset to koff. wA/wB hold
// the first two blocks (preloaded by caller before the previous barrier).
template <int KS>
__device__ __forceinline__ void gemmT4(const float* __restrict__ Wp,
                                       const float* __restrict__ bp,
                                       float4* __restrict__ wA,
                                       float4* __restrict__ wB,
                                       u64* __restrict__ acc)
{
#pragma unroll
    for (int i = 0; i < 16; i++) acc[i] = 0ull;

    ulonglong2 ua = *(const ulonglong2*)(bp);       // k-row 0: rows (0,1),(2,3)
    ulonglong2 ub = *(const ulonglong2*)(bp + 4);   //          rows (4,5),(6,7)

#pragma unroll
    for (int kb = 0; kb < KS; kb += 4) {
        float4 wN[4];
        const bool ldw = (kb + 8 < KS);
        if (ldw) {
#pragma unroll
            for (int j = 0; j < 4; j++) wN[j] = *(const float4*)(Wp + (kb + 8 + j) * H_N);
        }
#pragma unroll
        for (int j = 0; j < 4; j++) {
            if (kb + j >= KS) continue;                    // compile-time (KS=4 case)
            const int knext = kb + j + 1;
            ulonglong2 na, nb;
            const bool lda = (knext < KS);
            if (lda) {
                na = *(const ulonglong2*)(bp + knext * BST);
                nb = *(const ulonglong2*)(bp + knext * BST + 4);
            }
            u64 w0 = dup2(wA[j].x), w1 = dup2(wA[j].y);
            u64 w2 = dup2(wA[j].z), w3 = dup2(wA[j].w);
            acc[0]  = fma2(ua.x, w0, acc[0]);  acc[1]  = fma2(ua.y, w0, acc[1]);
            acc[2]  = fma2(ub.x, w0, acc[2]);  acc[3]  = fma2(ub.y, w0, acc[3]);
            acc[4]  = fma2(ua.x, w1, acc[4]);  acc[5]  = fma2(ua.y, w1, acc[5]);
            acc[6]  = fma2(ub.x, w1, acc[6]);  acc[7]  = fma2(ub.y, w1, acc[7]);
            acc[8]  = fma2(ua.x, w2, acc[8]);  acc[9]  = fma2(ua.y, w2, acc[9]);
            acc[10] = fma2(ub.x, w2, acc[10]); acc[11] = fma2(ub.y, w2, acc[11]);
            acc[12] = fma2(ua.x, w3, acc[12]); acc[13] = fma2(ua.y, w3, acc[13]);
            acc[14] = fma2(ub.x, w3, acc[14]); acc[15] = fma2(ub.y, w3, acc[15]);
            if (lda) { ua = na; ub = nb; }
        }
#pragma unroll
        for (int j = 0; j < 4; j++) wA[j] = wB[j];
        if (ldw) {
#pragma unroll
            for (int j = 0; j < 4; j++) wB[j] = wN[j];
        }
    }
}

// Deposit 32 raw floats (16 packed pairs) at redp: word layout c*8+m.
__device__ __forceinline__ void red_put(float* __restrict__ redp,
                                        const u64* __restrict__ acc)
{
#pragma unroll
    for (int c = 0; c < 4; c++) {
        *(ulonglong2*)(redp + c * 8)     = make_ulonglong2(acc[c * 4],     acc[c * 4 + 1]);
        *(ulonglong2*)(redp + c * 8 + 4) = make_ulonglong2(acc[c * 4 + 2], acc[c * 4 + 3]);
    }
}

// Sum the 8 group-partials for this thread's 4 values (2 packed pairs) via a
// packed-f32x2 tree. Returns {rows(m0,m0+1), rows(m0+2,m0+3)} of column n_e.
__device__ __forceinline__ ulonglong2 combine8p(const float* __restrict__ red,
                                                int ct_e, int off)
{
    const float* p = red + ct_e * RST + off;
    ulonglong2 v0 = *(const ulonglong2*)(p);
    ulonglong2 v1 = *(const ulonglong2*)(p + 1 * NCT * RST);
    ulonglong2 v2 = *(const ulonglong2*)(p + 2 * NCT * RST);
    ulonglong2 v3 = *(const ulonglong2*)(p + 3 * NCT * RST);
    ulonglong2 v4 = *(const ulonglong2*)(p + 4 * NCT * RST);
    ulonglong2 v5 = *(const ulonglong2*)(p + 5 * NCT * RST);
    ulonglong2 v6 = *(const ulonglong2*)(p + 6 * NCT * RST);
    ulonglong2 v7 = *(const ulonglong2*)(p + 7 * NCT * RST);
    u64 ax = add2(add2(add2(v0.x, v1.x), add2(v2.x, v3.x)),
                  add2(add2(v4.x, v5.x), add2(v6.x, v7.x)));
    u64 ay = add2(add2(add2(v0.y, v1.y), add2(v2.y, v3.y)),
                  add2(add2(v4.y, v5.y), add2(v6.y, v7.y)));
    return make_ulonglong2(ax, ay);
}

// Packed projection partial over one K-quarter: 2 output columns per thread.
__device__ __forceinline__ u64 proj_part2(const float* __restrict__ buf,
                                          const float* __restrict__ Wd,
                                          u64 bd2, int q, int r, int cp)
{
    u64 s2 = (q == 0) ? bd2 : 0ull;
    const int k0 = q * (H_N / 4);
    const float* wp = Wd + 2 * cp;
#pragma unroll 16
    for (int kk = k0; kk < k0 + H_N / 4; kk++) {
        u64 w = *(const u64*)(wp + kk * OUT_N);
        s2 = fma2(dup2(buf[kk * BST + r]), w, s2);
    }
    return s2;
}

__global__ void __launch_bounds__(NTH, 1)
cde_kernel(const float* __restrict__ coeffs, const float* __restrict__ times,
           const float* __restrict__ Wi,     const float* __restrict__ bi,
           const float* __restrict__ Wf,     const float* __restrict__ bfb,
           const float* __restrict__ Wd,     const float* __restrict__ bd,
           float* __restrict__ out)
{
    extern __shared__ float smem[];
    float* bufA = smem;                                  // 2048 floats
    float* bufB = smem + BUF_FLOATS;                     // 2048 floats
    float* red  = smem + 2 * BUF_FLOATS;                 // 18432 floats
    u64*   scr  = (u64*)(smem + 2 * BUF_FLOATS + RED_FLOATS);  // 3*128 u64
    float* tms  = smem + 2 * BUF_FLOATS + RED_FLOATS + SCR_FLOATS; // 128 floats

    const int tid   = threadIdx.x;
    const int kg    = tid >> 6;                 // split-K group 0..7
    const int ct    = tid & 63;                 // column-thread in group
    const int n0    = ct * 4;
    const int bbase = blockIdx.x * MC;

    // combine/update mapping: thread owns column n_e, rows m0..m0+3.
    const int ct_e = tid >> 3;
    const int sub  = tid & 7;
    const int c_e  = sub >> 1;
    const int m0   = (sub & 1) * 4;
    const int n_e  = ct_e * 4 + c_e;
    const int off  = c_e * 8 + m0;

    // projection mapping: 128 units (8 rows x 16 col-pairs) x 4 K-quarters
    const int p_q    = tid >> 7;                // K-quarter 0..3
    const int p_unit = tid & 127;
    const int p_r    = p_unit >> 4;             // batch row 0..7
    const int p_cp   = p_unit & 15;             // col-pair 0..15

    float* redp = red + (kg * NCT + ct) * RST;
    u64 acc[16];
    float4 wA[4], wB[4];

    // loop-invariant scalars hoisted off the combine critical path
    const u64 bias0 = dup2(bfb[0 * H_N + n_e]);
    const u64 bias1 = dup2(bfb[1 * H_N + n_e]);
    const u64 bias2 = dup2(bfb[2 * H_N + n_e]);
    const u64 bias3 = dup2(bfb[3 * H_N + n_e]);
    const u64 bd2   = *(const u64*)(bd + 2 * p_cp);

    // per-thread weight base for the hidden layers
    const size_t HH = (size_t)H_N * H_N;
    const float* W0 = Wf + (size_t)kg * KSH * H_N + n0;
    const int kact  = kg * KSH * BST;           // act offset for hidden GEMMs

    // hoisted output base for this thread's projection writes
    float* outp = out + (size_t)(bbase + p_r) * T_N * OUT_N + 2 * p_cp;

    // ---- stage coeffs[:,0,:] -> bufA[k][m]; stage times -> SMEM ----
    if (tid < 256) {
        int m = tid >> 5, kk = tid & 31;
        bufA[kk * BST + m] = coeffs[(size_t)(bbase + m) * T_N * IN_N + kk];
    } else if (tid < 256 + T_N) {
        tms[tid - 256] = times[tid - 256];
    }

    // preload init-GEMM weights (KSI=4: one block) while staging lands
    wpre<KSI>(Wi + (size_t)kg * KSI * H_N + n0, wA, wB);
    __syncthreads();

    // ---- y0 = coeffs0 @ Wi + bi ----
    u64 y01, y23, ks01, ks23;
    gemmT4<KSI>(Wi + (size_t)kg * KSI * H_N + n0, bufA + kg * KSI * BST, wA, wB, acc);
    red_put(redp, acc);
    wpre<KSH>(W0, wA, wB);                      // prefetch layer-0 weights
    __syncthreads();
    {
        ulonglong2 v = combine8p(red, ct_e, off);
        u64 bb = dup2(bi[n_e]);
        y01 = add2(v.x, bb); y23 = add2(v.y, bb);
        *(ulonglong2*)(bufA + n_e * BST + m0) = make_ulonglong2(y01, y23);
    }
    qbar(p_q);                  // quarter-local: proj+GEMM read own quarter

    // ---- time loop; proj of y_t folded into stage-0/layer-0 of step t ----
#pragma unroll 1
    for (int t = 0; t < T_N - 1; t++) {
        const float dt = tms[t + 1] - tms[t];

#pragma unroll 1
        for (int st = 0; st < 4; st++) {
            float* in = bufA; float* ob = bufB;
            u64 ps2 = 0ull;
#pragma unroll 1
            for (int l = 0; l < 3; l++) {
                if (st == 0 && l == 0) {
                    // projection partial of y_t (bufA stable through this GEMM)
                    ps2 = proj_part2(bufA, Wd, bd2, p_q, p_r, p_cp);
                    if (p_q) scr[(p_q - 1) * 128 + p_unit] = ps2;
                }
                gemmT4<KSH>(W0 + l * HH, in + kact, wA, wB, acc);
                red_put(redp, acc);
                wpre<KSH>(W0 + (l + 1) * HH, wA, wB);   // prefetch next layer
                __syncthreads();     // full: deposits cross all groups (+scr)
                if (st == 0 && l == 0 && p_q == 0) {
                    u64 s = add2(add2(ps2, scr[p_unit]),
                                 add2(scr[128 + p_unit], scr[256 + p_unit]));
                    *(float2*)(outp + (size_t)t * OUT_N) = unpk(s);
                }
                ulonglong2 vp = combine8p(red, ct_e, off);
                u64 bb = (l == 0) ? bias0 : (l == 1) ? bias1 : bias2;
                float2 lo = unpk(add2(vp.x, bb));
                float2 hi = unpk(add2(vp.y, bb));
                float4 v = make_float4(lipswish(lo.x), lipswish(lo.y),
                                       lipswish(hi.x), lipswish(hi.y));
                *(float4*)(ob + n_e * BST + m0) = v;
                gbar(kg);            // group-local: own GEMM reads own columns
                float* tmp = in; in = ob; ob = tmp;
            }
            gemmT4<KSH>(W0 + 3 * HH, in + kact, wA, wB, acc);
            red_put(redp, acc);
            wpre<KSH>(W0, wA, wB);                      // prefetch next stage L0
            __syncthreads();         // full: deposits cross all groups
            ulonglong2 kvp = combine8p(red, ct_e, off);
            u64 k01 = add2(kvp.x, bias3), k23 = add2(kvp.y, bias3);
            u64 s01, s23;
            if (st == 0) {
                ks01 = k01; ks23 = k23;
                u64 h = dup2(0.5f * dt);
                s01 = fma2(h, k01, y01); s23 = fma2(h, k23, y23);
            } else if (st == 1) {
                u64 two = dup2(2.f);
                ks01 = fma2(two, k01, ks01); ks23 = fma2(two, k23, ks23);
                u64 h = dup2(0.5f * dt);
                s01 = fma2(h, k01, y01); s23 = fma2(h, k23, y23);
            } else if (st == 2) {
                u64 two = dup2(2.f);
                ks01 = fma2(two, k01, ks01); ks23 = fma2(two, k23, ks23);
                u64 h = dup2(dt);
                s01 = fma2(h, k01, y01); s23 = fma2(h, k23, y23);
            } else {
                ks01 = add2(ks01, k01); ks23 = add2(ks23, k23);
                u64 h = dup2(dt * (1.f / 6.f));
                y01 = fma2(h, ks01, y01); y23 = fma2(h, ks23, y23);
                s01 = y01; s23 = y23;
            }
            *(ulonglong2*)(bufA + n_e * BST + m0) = make_ulonglong2(s01, s23);
            if (st < 3) gbar(kg);    // group-local: next stage L0 reads own cols
            else        qbar(p_q);   // quarter-local: st0/l0 proj+GEMM per quarter
        }
    }

    // ---- final projection of y_{T-1} ----
    {
        u64 ps2 = proj_part2(bufA, Wd, bd2, p_q, p_r, p_cp);
        if (p_q) scr[(p_q - 1) * 128 + p_unit] = ps2;
        __syncthreads();
        if (p_q == 0) {
            u64 s = add2(add2(ps2, scr[p_unit]),
                         add2(scr[128 + p_unit], scr[256 + p_unit]));
            *(float2*)(outp + (size_t)(T_N - 1) * OUT_N) = unpk(s);
        }
    }
}

extern "C" void kernel_launch(void* const* d_in, const int* in_sizes, int n_in,
                              void* d_out, int out_size)
{
    const float* coeffs = (const float*)d_in[0];
    const float* times  = (const float*)d_in[1];
    const float* Wi     = (const float*)d_in[2];
    const float* bi     = (const float*)d_in[3];
    const float* Wf     = (const float*)d_in[4];
    const float* bf     = (const float*)d_in[5];
    const float* Wd     = (const float*)d_in[6];
    const float* bd     = (const float*)d_in[7];
    float* out = (float*)d_out;

    cudaFuncSetAttribute(cde_kernel,
                         cudaFuncAttributeMaxDynamicSharedMemorySize, SMEM_BYTES);

    const int B    = in_sizes[0] / (T_N * IN_N);   // 1024
    const int grid = B / MC;                       // 128
    cde_kernel<<<grid, NTH, SMEM_BYTES>>>(coeffs, times, Wi, bi, Wf, bf, Wd, bd, out);
}